// round 10
// baseline (speedup 1.0000x reference)
#include <cuda_runtime.h>
#include <cuda.h>
#include <cuda_fp16.h>
#include <cstdint>

// ===================== constants =====================
#define NNODES   16384
#define HDIM     128
#define TILE_M   128
#define TILE_N   128

// ---- GEMM1 (fp32 A + fp16 B) ----
#define KSUPER   64
#define SSTAGES  4
#define SITERS   (NNODES / KSUPER)   // 256
#define A_SS_BYTES (TILE_M * KSUPER * 4)   // 32768
#define B_SS_BYTES (TILE_N * KSUPER * 2)   // 16384
#define SS_TX      (A_SS_BYTES + B_SS_BYTES)
#define SM_A       1024
#define SM_B       (SM_A + SSTAGES * A_SS_BYTES)
#define SMEM_TOTAL (SM_B + SSTAGES * B_SS_BYTES)     // 197632
#define BIG1_THREADS 352   // w0-7 compute, w8 TMA, w9-10 fp16-A writeback

// ---- GEMM2 (fp16 A + fp16 B) ----
#define K2SUPER  128
#define S2STAGES 3
#define S2ITERS  (NNODES / K2SUPER)  // 128
#define A2_SS_BYTES (TILE_M * K2SUPER * 2)  // 32768
#define B2_SS_BYTES (TILE_N * K2SUPER * 2)  // 32768
#define SS2_TX      (A2_SS_BYTES + B2_SS_BYTES)
#define SM2_A       1024
#define SM2_B       (SM2_A + S2STAGES * A2_SS_BYTES)
#define SMEM2_TOTAL (SM2_B + S2STAGES * B2_SS_BYTES)  // 197632
#define BIG2_THREADS 288

#define SM_FULL    0
#define SM_DONE    64
#define SM_CNT     128    // volatile pacing counter (int)

// in_gemm smem
#define XS_PAD  129
#define IN_SMEM ((HDIM * HDIM + HDIM * XS_PAD) * 4)

// scratch (allocation-free rule: __device__ globals)
__device__ __align__(1024) __half g_bufA16[16384UL * 16384];  // adjacency fp16
__device__ __align__(1024) __half g_bufB[128UL * 16384];      // t^T [H][N] fp16
__device__ __align__(1024) float  g_bufH[16384UL * 128];      // h   [N][H]

// ===================== PTX helpers =====================
__device__ __forceinline__ uint32_t smem_u32(const void* p) {
    uint32_t a;
    asm("{ .reg .u64 t; cvta.to.shared.u64 t, %1; cvt.u32.u64 %0, t; }" : "=r"(a) : "l"(p));
    return a;
}

#define MBAR_INIT(addr, cnt) \
    asm volatile("mbarrier.init.shared.b64 [%0], %1;" :: "r"(addr), "r"(cnt) : "memory")
#define MBAR_EXPECT_TX(addr, bytes) \
    asm volatile("mbarrier.arrive.expect_tx.shared.b64 _, [%0], %1;" :: "r"(addr), "r"(bytes) : "memory")
#define MBAR_ARRIVE(addr) \
    asm volatile("mbarrier.arrive.shared.b64 _, [%0];" :: "r"(addr) : "memory")

#define MBAR_WAIT(addr, parity) do {                                            \
    uint32_t _m = (addr), _p = (parity), _d;                                    \
    asm volatile("{\n\t.reg .pred p;\n\t"                                       \
        "mbarrier.try_wait.parity.acquire.cta.shared::cta.b64 p, [%1], %2;\n\t" \
        "selp.b32 %0, 1, 0, p;\n\t}" : "=r"(_d) : "r"(_m), "r"(_p) : "memory"); \
    if (!_d) {                                                                  \
        asm volatile("{\n\t.reg .pred P1;\n\t"                                  \
        "WL%=:\n\t"                                                             \
        "mbarrier.try_wait.parity.acquire.cta.shared::cta.b64 P1, [%0], %1, 0x989680;\n\t" \
        "@P1 bra.uni WD%=;\n\t"                                                 \
        "bra.uni WL%=;\n\t"                                                     \
        "WD%=:\n\t}" :: "r"(_m), "r"(_p) : "memory");                           \
    } } while (0)

__device__ __forceinline__ void tma_2d(uint32_t smem_dst, const CUtensorMap* map,
                                       int32_t cx, int32_t cy, uint32_t mbar) {
    asm volatile(
        "cp.async.bulk.tensor.2d.shared::cta.global.tile.mbarrier::complete_tx::bytes "
        "[%0], [%1, {%2, %3}], [%4];"
        :: "r"(smem_dst), "l"(map), "r"(cx), "r"(cy), "r"(mbar) : "memory");
}

__device__ __forceinline__ uint32_t pack_f16x2(float a, float b) {
    uint32_t r;
    asm("cvt.rn.f16x2.f32 %0, %1, %2;" : "=r"(r) : "f"(b), "f"(a));
    return r;
}

__device__ __forceinline__ void mma_f16(float* c, const uint32_t* a, uint32_t b0, uint32_t b1) {
    asm volatile("mma.sync.aligned.m16n8k16.row.col.f32.f16.f16.f32 "
        "{%0,%1,%2,%3}, {%4,%5,%6,%7}, {%8,%9}, {%0,%1,%2,%3};"
        : "+f"(c[0]), "+f"(c[1]), "+f"(c[2]), "+f"(c[3])
        : "r"(a[0]), "r"(a[1]), "r"(a[2]), "r"(a[3]), "r"(b0), "r"(b1));
}

// ===================== GEMM1: fp32 A (TMA) + fp16 B, fused fp16-A writeback =====================
__global__ void __launch_bounds__(BIG1_THREADS, 1)
gcn_big_gemm1(const __grid_constant__ CUtensorMap tmA,
              const __grid_constant__ CUtensorMap tmB,
              const float* __restrict__ bias,
              float* __restrict__ out,
              const float* __restrict__ adj,
              __half* __restrict__ a16) {
    extern __shared__ __align__(1024) char smem[];
    const uint32_t base = smem_u32(smem);
    const int tid  = threadIdx.x;
    const int wid  = tid >> 5;
    const int lane = tid & 31;
    const int m0   = blockIdx.x * TILE_M;

    volatile int* cnt = (volatile int*)(smem + SM_CNT);
    if (tid == 0) {
        for (int s = 0; s < SSTAGES; s++) {
            MBAR_INIT(base + SM_FULL + s * 8, 1);
            MBAR_INIT(base + SM_DONE + s * 8, 8);
        }
        *cnt = 0;
    }
    __syncthreads();

    if (wid == 8) {
        // -------- TMA producer --------
        if (lane == 0) {
            const CUtensorMap* pA = &tmA;
            const CUtensorMap* pB = &tmB;
            int ss = 0, ph = 1;
            for (int i = 0; i < SITERS; i++) {
                MBAR_WAIT(base + SM_DONE + ss * 8, (uint32_t)ph);
                uint32_t full = base + SM_FULL + ss * 8;
                MBAR_EXPECT_TX(full, SS_TX);
                uint32_t aslot = base + SM_A + ss * A_SS_BYTES;
                uint32_t bslot = base + SM_B + ss * B_SS_BYTES;
                int k0 = i * KSUPER;
                tma_2d(aslot,         pA, k0,      m0, full);
                tma_2d(aslot + 16384, pA, k0 + 32, m0, full);
                tma_2d(bslot,         pB, k0,      0,  full);
                if (++ss == SSTAGES) { ss = 0; ph ^= 1; }
            }
        }
    } else if (wid >= 9) {
        // -------- fp16-A writeback, paced by monotonic counter (deadlock-free).
        // counter >= j+1  =>  FULL(j) completed  =>  A slab for iter j is L2-hot.
        const int flat = (wid - 9) * 32 + lane;   // 0..63
        const int rsel = flat >> 4;               // 0..3
        const int kc   = (flat & 15) * 4;         // fp32 chunk within 64
        for (int j = 0; j < SITERS; j++) {
            while (*cnt < j + 1) __nanosleep(64);
            const size_t kbase = (size_t)j * KSUPER;
            #pragma unroll 4
            for (int r = rsel; r < TILE_M; r += 4) {
                const size_t off = (size_t)(m0 + r) * NNODES + kbase + kc;
                const float4 v = *reinterpret_cast<const float4*>(adj + off);
                __half2 h01 = __floats2half2_rn(v.x, v.y);
                __half2 h23 = __floats2half2_rn(v.z, v.w);
                uint2 st;
                st.x = *reinterpret_cast<const uint32_t*>(&h01);
                st.y = *reinterpret_cast<const uint32_t*>(&h23);
                *reinterpret_cast<uint2*>(a16 + off) = st;
            }
        }
    } else {
        // -------- compute warps (4x2 grid of 32x64 tiles) --------
        const int g  = lane >> 2;
        const int tg = lane & 3;
        const int wm = wid >> 1;
        const int wn = wid & 1;
        const uint32_t xorv = (uint32_t)g << 4;

        const uint32_t rAbase = (uint32_t)(wm * 32 + g) * 128;
        const uint32_t rBbase = (uint32_t)(wn * 64 + g) * 128;

        uint32_t cA[2][2];
        #pragma unroll
        for (int s = 0; s < 2; s++) {
            cA[s][0] = ((uint32_t)(s * 64 + 8 * tg)) ^ xorv;
            cA[s][1] = ((uint32_t)(s * 64 + 8 * tg + 32)) ^ xorv;
        }
        uint32_t cB[4][2];
        #pragma unroll
        for (int kb = 0; kb < 4; kb++) {
            cB[kb][0] = ((uint32_t)(32 * kb + 4 * tg)) ^ xorv;
            cB[kb][1] = ((uint32_t)(32 * kb + 16 + 4 * tg)) ^ xorv;
        }

        float acc[2][8][4];
        #pragma unroll
        for (int mi = 0; mi < 2; mi++)
            #pragma unroll
            for (int ni = 0; ni < 8; ni++)
                #pragma unroll
                for (int q = 0; q < 4; q++) acc[mi][ni][q] = 0.0f;

        uint32_t Af[2][2][4];
        uint32_t Bf[2][8][2];

        auto ldA = [&](uint32_t af[2][4], const char* astg, int kb) {
            const char* ab = astg + ((kb >> 1) << 14);
            const uint32_t* c = cA[kb & 1];
            #pragma unroll
            for (int mi = 0; mi < 2; mi++) {
                const char* r0 = ab + rAbase + mi * 2048;
                uint2 lo0 = *(const uint2*)(r0 + c[0]);
                uint2 lo1 = *(const uint2*)(r0 + 1024 + c[0]);
                uint2 hi0 = *(const uint2*)(r0 + c[1]);
                uint2 hi1 = *(const uint2*)(r0 + 1024 + c[1]);
                af[mi][0] = pack_f16x2(__uint_as_float(lo0.x), __uint_as_float(lo0.y));
                af[mi][1] = pack_f16x2(__uint_as_float(lo1.x), __uint_as_float(lo1.y));
                af[mi][2] = pack_f16x2(__uint_as_float(hi0.x), __uint_as_float(hi0.y));
                af[mi][3] = pack_f16x2(__uint_as_float(hi1.x), __uint_as_float(hi1.y));
            }
        };
        auto ldB = [&](uint32_t bf[8][2], const char* bstg, int kb) {
            #pragma unroll
            for (int ni = 0; ni < 8; ni++) {
                bf[ni][0] = *(const uint32_t*)(bstg + rBbase + ni * 1024 + cB[kb][0]);
                bf[ni][1] = *(const uint32_t*)(bstg + rBbase + ni * 1024 + cB[kb][1]);
            }
        };
        auto mmab = [&](const uint32_t af[2][4], const uint32_t bf[8][2]) {
            #pragma unroll
            for (int mi = 0; mi < 2; mi++)
                #pragma unroll
                for (int ni = 0; ni < 8; ni++)
                    mma_f16(acc[mi][ni], af[mi], bf[ni][0], bf[ni][1]);
        };

        int ss = 0, ph = 0;
        const char* astg = smem + SM_A;
        const char* bstg = smem + SM_B;

        MBAR_WAIT(base + SM_FULL, 0u);
        if (wid == 0 && lane == 0) *cnt = 1;
        ldB(Bf[0], bstg, 0);
        ldA(Af[0], astg, 0);

        for (int i = 0; i < SITERS; i++) {
            #pragma unroll
            for (int kb = 0; kb < 4; kb++) {
                if (kb < 3) {
                    const int nb = (kb + 1) & 1;
                    ldB(Bf[nb], bstg, kb + 1);
                    ldA(Af[nb], astg, kb + 1);
                    mmab(Af[kb & 1], Bf[kb & 1]);
                } else {
                    mmab(Af[1], Bf[1]);
                    if (lane == 0) MBAR_ARRIVE(base + SM_DONE + ss * 8);
                    int ssn = ss + 1, phn = ph;
                    if (ssn == SSTAGES) { ssn = 0; phn ^= 1; }
                    if (i < SITERS - 1) {
                        MBAR_WAIT(base + SM_FULL + ssn * 8, (uint32_t)phn);
                        if (wid == 0 && lane == 0) *cnt = i + 2;
                        astg = smem + SM_A + ssn * A_SS_BYTES;
                        bstg = smem + SM_B + ssn * B_SS_BYTES;
                        ldB(Bf[0], bstg, 0);
                        ldA(Af[0], astg, 0);
                    }
                    ss = ssn; ph = phn;
                }
            }
        }
        if (wid == 0 && lane == 0) *cnt = SITERS + SSTAGES;  // release any trailing waits

        // epilogue: bias + relu
        #pragma unroll
        for (int ni = 0; ni < 8; ni++) {
            const int c0 = wn * 64 + ni * 8 + tg * 2;
            const float bb0 = __ldg(&bias[c0]);
            const float bb1 = __ldg(&bias[c0 + 1]);
            #pragma unroll
            for (int mi = 0; mi < 2; mi++) {
                const int r0 = m0 + wm * 32 + mi * 16 + g;
                float2 v0, v1;
                v0.x = fmaxf(acc[mi][ni][0] + bb0, 0.0f);
                v0.y = fmaxf(acc[mi][ni][1] + bb1, 0.0f);
                v1.x = fmaxf(acc[mi][ni][2] + bb0, 0.0f);
                v1.y = fmaxf(acc[mi][ni][3] + bb1, 0.0f);
                *reinterpret_cast<float2*>(out + (size_t)r0 * HDIM + c0) = v0;
                *reinterpret_cast<float2*>(out + (size_t)(r0 + 8) * HDIM + c0) = v1;
            }
        }
    }
}

// ===================== GEMM2: fp16 A (TMA) + fp16 B, no cvt =====================
__global__ void __launch_bounds__(BIG2_THREADS, 1)
gcn_big_gemm2(const __grid_constant__ CUtensorMap tmA16,
              const __grid_constant__ CUtensorMap tmB,
              const float* __restrict__ bias,
              float* __restrict__ out) {
    extern __shared__ __align__(1024) char smem[];
    const uint32_t base = smem_u32(smem);
    const int tid  = threadIdx.x;
    const int wid  = tid >> 5;
    const int lane = tid & 31;
    const int m0   = blockIdx.x * TILE_M;

    if (tid == 0) {
        for (int s = 0; s < S2STAGES; s++) {
            MBAR_INIT(base + SM_FULL + s * 8, 1);
            MBAR_INIT(base + SM_DONE + s * 8, 8);
        }
    }
    __syncthreads();

    if (wid == 8) {
        if (lane == 0) {
            const CUtensorMap* pA = &tmA16;
            const CUtensorMap* pB = &tmB;
            int ss = 0, ph = 1;
            for (int i = 0; i < S2ITERS; i++) {
                MBAR_WAIT(base + SM_DONE + ss * 8, (uint32_t)ph);
                uint32_t full = base + SM_FULL + ss * 8;
                MBAR_EXPECT_TX(full, SS2_TX);
                uint32_t aslot = base + SM2_A + ss * A2_SS_BYTES;
                uint32_t bslot = base + SM2_B + ss * B2_SS_BYTES;
                int k0 = i * K2SUPER;
                tma_2d(aslot,         pA, k0,      m0, full);
                tma_2d(aslot + 16384, pA, k0 + 64, m0, full);
                tma_2d(bslot,         pB, k0,      0,  full);
                tma_2d(bslot + 16384, pB, k0 + 64, 0,  full);
                if (++ss == S2STAGES) { ss = 0; ph ^= 1; }
            }
        }
    } else {
        const int g  = lane >> 2;
        const int tg = lane & 3;
        const int wm = wid >> 1;      // 0..3
        const int wn = wid & 1;       // 0..1
        const uint32_t xorv = (uint32_t)g << 4;

        const uint32_t rAbase = (uint32_t)(wm * 32 + g) * 128;
        const uint32_t rBbase = (uint32_t)(wn * 64 + g) * 128;

        uint32_t cK[4][2];
        #pragma unroll
        for (int kb = 0; kb < 4; kb++) {
            cK[kb][0] = ((uint32_t)(32 * kb + 4 * tg)) ^ xorv;
            cK[kb][1] = ((uint32_t)(32 * kb + 16 + 4 * tg)) ^ xorv;
        }

        float acc[2][8][4];
        #pragma unroll
        for (int mi = 0; mi < 2; mi++)
            #pragma unroll
            for (int ni = 0; ni < 8; ni++)
                #pragma unroll
                for (int q = 0; q < 4; q++) acc[mi][ni][q] = 0.0f;

        uint32_t Af[2][2][4];
        uint32_t Bf[2][8][2];

        auto ldA = [&](uint32_t af[2][4], const char* astg, int kb) {
            const char* ab = astg + ((kb >> 2) << 14);
            const uint32_t* c = cK[kb & 3];
            #pragma unroll
            for (int mi = 0; mi < 2; mi++) {
                const char* r0 = ab + rAbase + mi * 2048;
                af[mi][0] = *(const uint32_t*)(r0 + c[0]);
                af[mi][1] = *(const uint32_t*)(r0 + 1024 + c[0]);
                af[mi][2] = *(const uint32_t*)(r0 + c[1]);
                af[mi][3] = *(const uint32_t*)(r0 + 1024 + c[1]);
            }
        };
        auto ldB = [&](uint32_t bf[8][2], const char* bstg, int kb) {
            const char* bb = bstg + ((kb >> 2) << 14);
            const uint32_t* c = cK[kb & 3];
            #pragma unroll
            for (int ni = 0; ni < 8; ni++) {
                bf[ni][0] = *(const uint32_t*)(bb + rBbase + ni * 1024 + c[0]);
                bf[ni][1] = *(const uint32_t*)(bb + rBbase + ni * 1024 + c[1]);
            }
        };
        auto mmab = [&](const uint32_t af[2][4], const uint32_t bf[8][2]) {
            #pragma unroll
            for (int mi = 0; mi < 2; mi++)
                #pragma unroll
                for (int ni = 0; ni < 8; ni++)
                    mma_f16(acc[mi][ni], af[mi], bf[ni][0], bf[ni][1]);
        };

        int ss = 0, ph = 0;
        const char* astg = smem + SM2_A;
        const char* bstg = smem + SM2_B;

        MBAR_WAIT(base + SM_FULL, 0u);
        ldB(Bf[0], bstg, 0);
        ldA(Af[0], astg, 0);

        for (int i = 0; i < S2ITERS; i++) {
            #pragma unroll
            for (int kb = 0; kb < 8; kb++) {
                if (kb < 7) {
                    const int nb = (kb + 1) & 1;
                    ldB(Bf[nb], bstg, kb + 1);
                    ldA(Af[nb], astg, kb + 1);
                    mmab(Af[kb & 1], Bf[kb & 1]);
                } else {
                    mmab(Af[1], Bf[1]);
                    if (lane == 0) MBAR_ARRIVE(base + SM_DONE + ss * 8);
                    int ssn = ss + 1, phn = ph;
                    if (ssn == S2STAGES) { ssn = 0; phn ^= 1; }
                    if (i < S2ITERS - 1) {
                        MBAR_WAIT(base + SM_FULL + ssn * 8, (uint32_t)phn);
                        astg = smem + SM2_A + ssn * A2_SS_BYTES;
                        bstg = smem + SM2_B + ssn * B2_SS_BYTES;
                        ldB(Bf[0], bstg, 0);
                        ldA(Af[0], astg, 0);
                    }
                    ss = ssn; ph = phn;
                }
            }
        }

        #pragma unroll
        for (int ni = 0; ni < 8; ni++) {
            const int c0 = wn * 64 + ni * 8 + tg * 2;
            const float bb0 = __ldg(&bias[c0]);
            const float bb1 = __ldg(&bias[c0 + 1]);
            #pragma unroll
            for (int mi = 0; mi < 2; mi++) {
                const int r0 = m0 + wm * 32 + mi * 16 + g;
                float2 v0, v1;
                v0.x = fmaxf(acc[mi][ni][0] + bb0, 0.0f);
                v0.y = fmaxf(acc[mi][ni][1] + bb1, 0.0f);
                v1.x = fmaxf(acc[mi][ni][2] + bb0, 0.0f);
                v1.y = fmaxf(acc[mi][ni][3] + bb1, 0.0f);
                *reinterpret_cast<float2*>(out + (size_t)r0 * HDIM + c0) = v0;
                *reinterpret_cast<float2*>(out + (size_t)(r0 + 8) * HDIM + c0) = v1;
            }
        }
    }
}

// ===================== small GEMM: outT[n][node] = sum_f in[node][f] * w[f][n] (fp16 out) =====================
__global__ void __launch_bounds__(256)
gcn_in_gemm(const float* __restrict__ in, const float* __restrict__ w, __half* __restrict__ outT) {
    extern __shared__ float sm[];
    float* ws = sm;
    float* xs = sm + HDIM * HDIM;
    const int tid = threadIdx.x;
    const int n0 = blockIdx.x * 128;

    for (int i = tid; i < (HDIM * HDIM) / 4; i += 256)
        reinterpret_cast<float4*>(ws)[i] = reinterpret_cast<const float4*>(w)[i];
    {
        const int col = tid & 127;
        const int r0  = tid >> 7;
        for (int r = r0; r < 128; r += 2)
            xs[r * XS_PAD + col] = in[(size_t)(n0 + r) * HDIM + col];
    }
    __syncthreads();

    const int cg   = tid >> 5;
    const int lane = tid & 31;

    float acc[4][16];
    #pragma unroll
    for (int k = 0; k < 4; k++)
        #pragma unroll
        for (int j = 0; j < 16; j++) acc[k][j] = 0.0f;

    #pragma unroll 4
    for (int f = 0; f < HDIM; f++) {
        float a[4];
        #pragma unroll
        for (int k = 0; k < 4; k++)
            a[k] = xs[(lane + 32 * k) * XS_PAD + f];
        const float4* wr = reinterpret_cast<const float4*>(ws + f * HDIM + cg * 16);
        float4 w0 = wr[0], w1 = wr[1], w2 = wr[2], w3 = wr[3];
        #pragma unroll
        for (int k = 0; k < 4; k++) {
            acc[k][0]  += a[k] * w0.x;  acc[k][1]  += a[k] * w0.y;
            acc[k][2]  += a[k] * w0.z;  acc[k][3]  += a[k] * w0.w;
            acc[k][4]  += a[k] * w1.x;  acc[k][5]  += a[k] * w1.y;
            acc[k][6]  += a[k] * w1.z;  acc[k][7]  += a[k] * w1.w;
            acc[k][8]  += a[k] * w2.x;  acc[k][9]  += a[k] * w2.y;
            acc[k][10] += a[k] * w2.z;  acc[k][11] += a[k] * w2.w;
            acc[k][12] += a[k] * w3.x;  acc[k][13] += a[k] * w3.y;
            acc[k][14] += a[k] * w3.z;  acc[k][15] += a[k] * w3.w;
        }
    }
    #pragma unroll
    for (int j = 0; j < 16; j++) {
        const int col = cg * 16 + j;
        #pragma unroll
        for (int k = 0; k < 4; k++)
            outT[(size_t)col * NNODES + n0 + lane + 32 * k] = __float2half_rn(acc[k][j]);
    }
}

// ===================== head =====================
__global__ void __launch_bounds__(256)
gcn_head(const float* __restrict__ h, const float* __restrict__ w3,
         const float* __restrict__ b3, float* __restrict__ out) {
    const int i = blockIdx.x * 256 + threadIdx.x;
    if (i >= NNODES) return;
    float s0 = __ldg(&b3[0]), s1 = __ldg(&b3[1]);
    const float4* hv = reinterpret_cast<const float4*>(h + (size_t)i * HDIM);
    #pragma unroll
    for (int q = 0; q < 32; q++) {
        float4 v = __ldg(&hv[q]);
        const int n = q * 4;
        s0 += v.x * __ldg(&w3[(n + 0) * 2 + 0]); s1 += v.x * __ldg(&w3[(n + 0) * 2 + 1]);
        s0 += v.y * __ldg(&w3[(n + 1) * 2 + 0]); s1 += v.y * __ldg(&w3[(n + 1) * 2 + 1]);
        s0 += v.z * __ldg(&w3[(n + 2) * 2 + 0]); s1 += v.z * __ldg(&w3[(n + 2) * 2 + 1]);
        s0 += v.w * __ldg(&w3[(n + 3) * 2 + 0]); s1 += v.w * __ldg(&w3[(n + 3) * 2 + 1]);
    }
    out[i * 2 + 0] = s0;
    out[i * 2 + 1] = s1;
}

// ===================== host =====================
typedef CUresult (*PFN_encodeTiled)(CUtensorMap*, CUtensorMapDataType, cuuint32_t, void*,
                                    const cuuint64_t*, const cuuint64_t*, const cuuint32_t*,
                                    const cuuint32_t*, CUtensorMapInterleave, CUtensorMapSwizzle,
                                    CUtensorMapL2promotion, CUtensorMapFloatOOBfill);

extern "C" void kernel_launch(void* const* d_in, const int* in_sizes, int n_in,
                              void* d_out, int out_size) {
    const float* x   = (const float*)d_in[0];
    const float* adj = (const float*)d_in[1];
    const float* w1  = (const float*)d_in[2];
    const float* b1  = (const float*)d_in[3];
    const float* w2  = (const float*)d_in[4];
    const float* b2  = (const float*)d_in[5];
    const float* w3  = (const float*)d_in[6];
    const float* b3  = (const float*)d_in[7];
    float* out = (float*)d_out;

    void *bufA16 = nullptr, *bufB = nullptr, *bufH = nullptr;
    cudaGetSymbolAddress(&bufA16, g_bufA16);
    cudaGetSymbolAddress(&bufB, g_bufB);
    cudaGetSymbolAddress(&bufH, g_bufH);

    void* fn = nullptr;
    cudaDriverEntryPointQueryResult qres;
    cudaGetDriverEntryPointByVersion("cuTensorMapEncodeTiled", &fn, 12000,
                                     cudaEnableDefault, &qres);
    PFN_encodeTiled encode = (PFN_encodeTiled)fn;

    CUtensorMap tmA{}, tmB{}, tmA16{};
    {
        cuuint64_t dims[2]   = {NNODES, NNODES};
        cuuint64_t stride[1] = {NNODES * sizeof(float)};
        cuuint32_t box[2]    = {32, TILE_M};
        cuuint32_t es[2]     = {1, 1};
        encode(&tmA, CU_TENSOR_MAP_DATA_TYPE_FLOAT32, 2, (void*)adj, dims, stride, box, es,
               CU_TENSOR_MAP_INTERLEAVE_NONE, CU_TENSOR_MAP_SWIZZLE_128B,
               CU_TENSOR_MAP_L2_PROMOTION_L2_128B, CU_TENSOR_MAP_FLOAT_OOB_FILL_NONE);
    }
    {
        cuuint64_t dims[2]   = {NNODES, HDIM};
        cuuint64_t stride[1] = {NNODES * sizeof(__half)};
        cuuint32_t box[2]    = {64, TILE_N};
        cuuint32_t es[2]     = {1, 1};
        encode(&tmB, CU_TENSOR_MAP_DATA_TYPE_FLOAT16, 2, bufB, dims, stride, box, es,
               CU_TENSOR_MAP_INTERLEAVE_NONE, CU_TENSOR_MAP_SWIZZLE_128B,
               CU_TENSOR_MAP_L2_PROMOTION_L2_128B, CU_TENSOR_MAP_FLOAT_OOB_FILL_NONE);
    }
    {
        cuuint64_t dims[2]   = {NNODES, NNODES};
        cuuint64_t stride[1] = {NNODES * sizeof(__half)};
        cuuint32_t box[2]    = {64, TILE_M};
        cuuint32_t es[2]     = {1, 1};
        encode(&tmA16, CU_TENSOR_MAP_DATA_TYPE_FLOAT16, 2, bufA16, dims, stride, box, es,
               CU_TENSOR_MAP_INTERLEAVE_NONE, CU_TENSOR_MAP_SWIZZLE_128B,
               CU_TENSOR_MAP_L2_PROMOTION_L2_128B, CU_TENSOR_MAP_FLOAT_OOB_FILL_NONE);
    }

    cudaFuncSetAttribute(gcn_big_gemm1, cudaFuncAttributeMaxDynamicSharedMemorySize, SMEM_TOTAL);
    cudaFuncSetAttribute(gcn_big_gemm2, cudaFuncAttributeMaxDynamicSharedMemorySize, SMEM2_TOTAL);
    cudaFuncSetAttribute(gcn_in_gemm, cudaFuncAttributeMaxDynamicSharedMemorySize, IN_SMEM);

    // 1) t1^T (fp16)
    gcn_in_gemm<<<NNODES / 128, 256, IN_SMEM>>>(x, w1, (__half*)bufB);
    // 2) h1 = relu(adj @ t1 + b1)  + fused adjacency->fp16 writeback
    gcn_big_gemm1<<<NNODES / TILE_M, BIG1_THREADS, SMEM_TOTAL>>>(
        tmA, tmB, b1, (float*)bufH, adj, (__half*)bufA16);
    // 3) t2^T (fp16)
    gcn_in_gemm<<<NNODES / 128, 256, IN_SMEM>>>((const float*)bufH, w2, (__half*)bufB);
    // 4) h2 = relu(adj16 @ t2 + b2)  (all-fp16 operands)
    gcn_big_gemm2<<<NNODES / TILE_M, BIG2_THREADS, SMEM2_TOTAL>>>(
        tmA16, tmB, b2, (float*)bufH);
    // 5) out = h2 @ w3 + b3
    gcn_head<<<NNODES / 256, 256>>>((const float*)bufH, w3, b3, out);
}

// round 11
// speedup vs baseline: 2.4484x; 2.4484x over previous
#include <cuda_runtime.h>
#include <cuda.h>
#include <cuda_fp16.h>
#include <cstdint>

// ===================== constants =====================
#define NNODES   16384
#define HDIM     128
#define TILE_M   128
#define TILE_N   128

// ---- GEMM1 (fp32 A + fp16 B) ----
#define KSUPER   64
#define SSTAGES  4
#define SITERS   (NNODES / KSUPER)   // 256
#define A_SS_BYTES (TILE_M * KSUPER * 4)   // 32768
#define B_SS_BYTES (TILE_N * KSUPER * 2)   // 16384
#define SS_TX      (A_SS_BYTES + B_SS_BYTES)
#define SM_A       1024
#define SM_B       (SM_A + SSTAGES * A_SS_BYTES)
#define SMEM_TOTAL (SM_B + SSTAGES * B_SS_BYTES)     // 197632
#define BIG1_THREADS 352   // w0-7 compute, w8 TMA, w9-10 smem->fp16 writeback

// ---- GEMM2 (fp16 A + fp16 B) ----
#define K2SUPER  128
#define S2STAGES 3
#define S2ITERS  (NNODES / K2SUPER)  // 128
#define A2_SS_BYTES (TILE_M * K2SUPER * 2)  // 32768
#define B2_SS_BYTES (TILE_N * K2SUPER * 2)  // 32768
#define SS2_TX      (A2_SS_BYTES + B2_SS_BYTES)
#define SM2_A       1024
#define SM2_B       (SM2_A + S2STAGES * A2_SS_BYTES)
#define SMEM2_TOTAL (SM2_B + S2STAGES * B2_SS_BYTES)  // 197632
#define BIG2_THREADS 288

#define SM_FULL    0
#define SM_DONE    64

// in_gemm smem
#define XS_PAD  129
#define IN_SMEM ((HDIM * HDIM + HDIM * XS_PAD) * 4)

// scratch (allocation-free rule: __device__ globals)
__device__ __align__(1024) __half g_bufA16[16384UL * 16384];  // adjacency fp16
__device__ __align__(1024) __half g_bufB[128UL * 16384];      // t^T [H][N] fp16
__device__ __align__(1024) float  g_bufH[16384UL * 128];      // h   [N][H]

// ===================== PTX helpers =====================
__device__ __forceinline__ uint32_t smem_u32(const void* p) {
    uint32_t a;
    asm("{ .reg .u64 t; cvta.to.shared.u64 t, %1; cvt.u32.u64 %0, t; }" : "=r"(a) : "l"(p));
    return a;
}

#define MBAR_INIT(addr, cnt) \
    asm volatile("mbarrier.init.shared.b64 [%0], %1;" :: "r"(addr), "r"(cnt) : "memory")
#define MBAR_EXPECT_TX(addr, bytes) \
    asm volatile("mbarrier.arrive.expect_tx.shared.b64 _, [%0], %1;" :: "r"(addr), "r"(bytes) : "memory")
#define MBAR_ARRIVE(addr) \
    asm volatile("mbarrier.arrive.shared.b64 _, [%0];" :: "r"(addr) : "memory")

#define MBAR_WAIT(addr, parity) do {                                            \
    uint32_t _m = (addr), _p = (parity), _d;                                    \
    asm volatile("{\n\t.reg .pred p;\n\t"                                       \
        "mbarrier.try_wait.parity.acquire.cta.shared::cta.b64 p, [%1], %2;\n\t" \
        "selp.b32 %0, 1, 0, p;\n\t}" : "=r"(_d) : "r"(_m), "r"(_p) : "memory"); \
    if (!_d) {                                                                  \
        asm volatile("{\n\t.reg .pred P1;\n\t"                                  \
        "WL%=:\n\t"                                                             \
        "mbarrier.try_wait.parity.acquire.cta.shared::cta.b64 P1, [%0], %1, 0x989680;\n\t" \
        "@P1 bra.uni WD%=;\n\t"                                                 \
        "bra.uni WL%=;\n\t"                                                     \
        "WD%=:\n\t}" :: "r"(_m), "r"(_p) : "memory");                           \
    } } while (0)

__device__ __forceinline__ void tma_2d(uint32_t smem_dst, const CUtensorMap* map,
                                       int32_t cx, int32_t cy, uint32_t mbar) {
    asm volatile(
        "cp.async.bulk.tensor.2d.shared::cta.global.tile.mbarrier::complete_tx::bytes "
        "[%0], [%1, {%2, %3}], [%4];"
        :: "r"(smem_dst), "l"(map), "r"(cx), "r"(cy), "r"(mbar) : "memory");
}

__device__ __forceinline__ uint32_t pack_f16x2(float a, float b) {
    uint32_t r;
    asm("cvt.rn.f16x2.f32 %0, %1, %2;" : "=r"(r) : "f"(b), "f"(a));
    return r;
}

__device__ __forceinline__ void mma_f16(float* c, const uint32_t* a, uint32_t b0, uint32_t b1) {
    asm volatile("mma.sync.aligned.m16n8k16.row.col.f32.f16.f16.f32 "
        "{%0,%1,%2,%3}, {%4,%5,%6,%7}, {%8,%9}, {%0,%1,%2,%3};"
        : "+f"(c[0]), "+f"(c[1]), "+f"(c[2]), "+f"(c[3])
        : "r"(a[0]), "r"(a[1]), "r"(a[2]), "r"(a[3]), "r"(b0), "r"(b1));
}

// ===================== GEMM1: fp32 A (TMA) + fp16 B, fused smem->fp16 A writeback =====================
__global__ void __launch_bounds__(BIG1_THREADS, 1)
gcn_big_gemm1(const __grid_constant__ CUtensorMap tmA,
              const __grid_constant__ CUtensorMap tmB,
              const float* __restrict__ bias,
              float* __restrict__ out,
              __half* __restrict__ a16) {
    extern __shared__ __align__(1024) char smem[];
    const uint32_t base = smem_u32(smem);
    const int tid  = threadIdx.x;
    const int wid  = tid >> 5;
    const int lane = tid & 31;
    const int m0   = blockIdx.x * TILE_M;

    if (tid == 0) {
        for (int s = 0; s < SSTAGES; s++) {
            MBAR_INIT(base + SM_FULL + s * 8, 1);
            MBAR_INIT(base + SM_DONE + s * 8, 10);   // 8 compute + 2 writeback
        }
    }
    __syncthreads();

    if (wid == 8) {
        // -------- TMA producer --------
        if (lane == 0) {
            const CUtensorMap* pA = &tmA;
            const CUtensorMap* pB = &tmB;
            int ss = 0, ph = 1;
            for (int i = 0; i < SITERS; i++) {
                MBAR_WAIT(base + SM_DONE + ss * 8, (uint32_t)ph);
                uint32_t full = base + SM_FULL + ss * 8;
                MBAR_EXPECT_TX(full, SS_TX);
                uint32_t aslot = base + SM_A + ss * A_SS_BYTES;
                uint32_t bslot = base + SM_B + ss * B_SS_BYTES;
                int k0 = i * KSUPER;
                tma_2d(aslot,         pA, k0,      m0, full);
                tma_2d(aslot + 16384, pA, k0 + 32, m0, full);
                tma_2d(bslot,         pB, k0,      0,  full);
                if (++ss == SSTAGES) { ss = 0; ph ^= 1; }
            }
        }
    } else if (wid >= 9) {
        // -------- fp16-A writeback: reads the fp32 A stage from SMEM (never gmem),
        // converts, stores fp16. A full pipeline consumer: waits FULL, arrives DONE.
        // Rows: warp9 -> lane, lane+32 ; warp10 -> lane+64, lane+96
        // (quarter-warp rows r..r+7 => (r&7)<<4 xor distinct => conflict-free LDS.128)
        const int r0 = (wid - 9) * 64 + lane;
        int ss = 0, ph = 0;
        for (int i = 0; i < SITERS; i++) {
            MBAR_WAIT(base + SM_FULL + ss * 8, (uint32_t)ph);
            const char* astg = smem + SM_A + ss * A_SS_BYTES;
            const size_t kbase = (size_t)i * KSUPER;
            #pragma unroll
            for (int rr = 0; rr < 2; rr++) {
                const int r = r0 + rr * 32;
                const uint32_t xorR = (uint32_t)(r & 7) << 4;
                __half* dst = a16 + (size_t)(m0 + r) * NNODES + kbase;
                #pragma unroll
                for (int b = 0; b < 2; b++) {
                    const char* rowp = astg + b * 16384 + r * 128;
                    #pragma unroll
                    for (int c = 0; c < 8; c += 2) {
                        float4 v0 = *(const float4*)(rowp + (((uint32_t)(c * 16)) ^ xorR));
                        float4 v1 = *(const float4*)(rowp + (((uint32_t)((c + 1) * 16)) ^ xorR));
                        uint4 o;
                        o.x = pack_f16x2(v0.x, v0.y);
                        o.y = pack_f16x2(v0.z, v0.w);
                        o.z = pack_f16x2(v1.x, v1.y);
                        o.w = pack_f16x2(v1.z, v1.w);
                        *reinterpret_cast<uint4*>(dst + b * 32 + c * 4) = o;
                    }
                }
            }
            if (lane == 0) MBAR_ARRIVE(base + SM_DONE + ss * 8);
            if (++ss == SSTAGES) { ss = 0; ph ^= 1; }
        }
    } else {
        // -------- compute warps (4x2 grid of 32x64 tiles) --------
        const int g  = lane >> 2;
        const int tg = lane & 3;
        const int wm = wid >> 1;
        const int wn = wid & 1;
        const uint32_t xorv = (uint32_t)g << 4;

        const uint32_t rAbase = (uint32_t)(wm * 32 + g) * 128;
        const uint32_t rBbase = (uint32_t)(wn * 64 + g) * 128;

        uint32_t cA[2][2];
        #pragma unroll
        for (int s = 0; s < 2; s++) {
            cA[s][0] = ((uint32_t)(s * 64 + 8 * tg)) ^ xorv;
            cA[s][1] = ((uint32_t)(s * 64 + 8 * tg + 32)) ^ xorv;
        }
        uint32_t cB[4][2];
        #pragma unroll
        for (int kb = 0; kb < 4; kb++) {
            cB[kb][0] = ((uint32_t)(32 * kb + 4 * tg)) ^ xorv;
            cB[kb][1] = ((uint32_t)(32 * kb + 16 + 4 * tg)) ^ xorv;
        }

        float acc[2][8][4];
        #pragma unroll
        for (int mi = 0; mi < 2; mi++)
            #pragma unroll
            for (int ni = 0; ni < 8; ni++)
                #pragma unroll
                for (int q = 0; q < 4; q++) acc[mi][ni][q] = 0.0f;

        uint32_t Af[2][2][4];
        uint32_t Bf[2][8][2];

        auto ldA = [&](uint32_t af[2][4], const char* astg, int kb) {
            const char* ab = astg + ((kb >> 1) << 14);
            const uint32_t* c = cA[kb & 1];
            #pragma unroll
            for (int mi = 0; mi < 2; mi++) {
                const char* r0p = ab + rAbase + mi * 2048;
                uint2 lo0 = *(const uint2*)(r0p + c[0]);
                uint2 lo1 = *(const uint2*)(r0p + 1024 + c[0]);
                uint2 hi0 = *(const uint2*)(r0p + c[1]);
                uint2 hi1 = *(const uint2*)(r0p + 1024 + c[1]);
                af[mi][0] = pack_f16x2(__uint_as_float(lo0.x), __uint_as_float(lo0.y));
                af[mi][1] = pack_f16x2(__uint_as_float(lo1.x), __uint_as_float(lo1.y));
                af[mi][2] = pack_f16x2(__uint_as_float(hi0.x), __uint_as_float(hi0.y));
                af[mi][3] = pack_f16x2(__uint_as_float(hi1.x), __uint_as_float(hi1.y));
            }
        };
        auto ldB = [&](uint32_t bf[8][2], const char* bstg, int kb) {
            #pragma unroll
            for (int ni = 0; ni < 8; ni++) {
                bf[ni][0] = *(const uint32_t*)(bstg + rBbase + ni * 1024 + cB[kb][0]);
                bf[ni][1] = *(const uint32_t*)(bstg + rBbase + ni * 1024 + cB[kb][1]);
            }
        };
        auto mmab = [&](const uint32_t af[2][4], const uint32_t bf[8][2]) {
            #pragma unroll
            for (int mi = 0; mi < 2; mi++)
                #pragma unroll
                for (int ni = 0; ni < 8; ni++)
                    mma_f16(acc[mi][ni], af[mi], bf[ni][0], bf[ni][1]);
        };

        int ss = 0, ph = 0;
        const char* astg = smem + SM_A;
        const char* bstg = smem + SM_B;

        MBAR_WAIT(base + SM_FULL, 0u);
        ldB(Bf[0], bstg, 0);
        ldA(Af[0], astg, 0);

        for (int i = 0; i < SITERS; i++) {
            #pragma unroll
            for (int kb = 0; kb < 4; kb++) {
                if (kb < 3) {
                    const int nb = (kb + 1) & 1;
                    ldB(Bf[nb], bstg, kb + 1);
                    ldA(Af[nb], astg, kb + 1);
                    mmab(Af[kb & 1], Bf[kb & 1]);
                } else {
                    mmab(Af[1], Bf[1]);
                    if (lane == 0) MBAR_ARRIVE(base + SM_DONE + ss * 8);
                    int ssn = ss + 1, phn = ph;
                    if (ssn == SSTAGES) { ssn = 0; phn ^= 1; }
                    if (i < SITERS - 1) {
                        MBAR_WAIT(base + SM_FULL + ssn * 8, (uint32_t)phn);
                        astg = smem + SM_A + ssn * A_SS_BYTES;
                        bstg = smem + SM_B + ssn * B_SS_BYTES;
                        ldB(Bf[0], bstg, 0);
                        ldA(Af[0], astg, 0);
                    }
                    ss = ssn; ph = phn;
                }
            }
        }

        // epilogue: bias + relu
        #pragma unroll
        for (int ni = 0; ni < 8; ni++) {
            const int c0 = wn * 64 + ni * 8 + tg * 2;
            const float bb0 = __ldg(&bias[c0]);
            const float bb1 = __ldg(&bias[c0 + 1]);
            #pragma unroll
            for (int mi = 0; mi < 2; mi++) {
                const int r0 = m0 + wm * 32 + mi * 16 + g;
                float2 v0, v1;
                v0.x = fmaxf(acc[mi][ni][0] + bb0, 0.0f);
                v0.y = fmaxf(acc[mi][ni][1] + bb1, 0.0f);
                v1.x = fmaxf(acc[mi][ni][2] + bb0, 0.0f);
                v1.y = fmaxf(acc[mi][ni][3] + bb1, 0.0f);
                *reinterpret_cast<float2*>(out + (size_t)r0 * HDIM + c0) = v0;
                *reinterpret_cast<float2*>(out + (size_t)(r0 + 8) * HDIM + c0) = v1;
            }
        }
    }
}

// ===================== GEMM2: fp16 A (TMA) + fp16 B, no cvt =====================
__global__ void __launch_bounds__(BIG2_THREADS, 1)
gcn_big_gemm2(const __grid_constant__ CUtensorMap tmA16,
              const __grid_constant__ CUtensorMap tmB,
              const float* __restrict__ bias,
              float* __restrict__ out) {
    extern __shared__ __align__(1024) char smem[];
    const uint32_t base = smem_u32(smem);
    const int tid  = threadIdx.x;
    const int wid  = tid >> 5;
    const int lane = tid & 31;
    const int m0   = blockIdx.x * TILE_M;

    if (tid == 0) {
        for (int s = 0; s < S2STAGES; s++) {
            MBAR_INIT(base + SM_FULL + s * 8, 1);
            MBAR_INIT(base + SM_DONE + s * 8, 8);
        }
    }
    __syncthreads();

    if (wid == 8) {
        if (lane == 0) {
            const CUtensorMap* pA = &tmA16;
            const CUtensorMap* pB = &tmB;
            int ss = 0, ph = 1;
            for (int i = 0; i < S2ITERS; i++) {
                MBAR_WAIT(base + SM_DONE + ss * 8, (uint32_t)ph);
                uint32_t full = base + SM_FULL + ss * 8;
                MBAR_EXPECT_TX(full, SS2_TX);
                uint32_t aslot = base + SM2_A + ss * A2_SS_BYTES;
                uint32_t bslot = base + SM2_B + ss * B2_SS_BYTES;
                int k0 = i * K2SUPER;
                tma_2d(aslot,         pA, k0,      m0, full);
                tma_2d(aslot + 16384, pA, k0 + 64, m0, full);
                tma_2d(bslot,         pB, k0,      0,  full);
                tma_2d(bslot + 16384, pB, k0 + 64, 0,  full);
                if (++ss == S2STAGES) { ss = 0; ph ^= 1; }
            }
        }
    } else {
        const int g  = lane >> 2;
        const int tg = lane & 3;
        const int wm = wid >> 1;      // 0..3
        const int wn = wid & 1;       // 0..1
        const uint32_t xorv = (uint32_t)g << 4;

        const uint32_t rAbase = (uint32_t)(wm * 32 + g) * 128;
        const uint32_t rBbase = (uint32_t)(wn * 64 + g) * 128;

        uint32_t cK[4][2];
        #pragma unroll
        for (int kb = 0; kb < 4; kb++) {
            cK[kb][0] = ((uint32_t)(32 * kb + 4 * tg)) ^ xorv;
            cK[kb][1] = ((uint32_t)(32 * kb + 16 + 4 * tg)) ^ xorv;
        }

        float acc[2][8][4];
        #pragma unroll
        for (int mi = 0; mi < 2; mi++)
            #pragma unroll
            for (int ni = 0; ni < 8; ni++)
                #pragma unroll
                for (int q = 0; q < 4; q++) acc[mi][ni][q] = 0.0f;

        uint32_t Af[2][2][4];
        uint32_t Bf[2][8][2];

        auto ldA = [&](uint32_t af[2][4], const char* astg, int kb) {
            const char* ab = astg + ((kb >> 2) << 14);
            const uint32_t* c = cK[kb & 3];
            #pragma unroll
            for (int mi = 0; mi < 2; mi++) {
                const char* r0p = ab + rAbase + mi * 2048;
                af[mi][0] = *(const uint32_t*)(r0p + c[0]);
                af[mi][1] = *(const uint32_t*)(r0p + 1024 + c[0]);
                af[mi][2] = *(const uint32_t*)(r0p + c[1]);
                af[mi][3] = *(const uint32_t*)(r0p + 1024 + c[1]);
            }
        };
        auto ldB = [&](uint32_t bf[8][2], const char* bstg, int kb) {
            const char* bb = bstg + ((kb >> 2) << 14);
            const uint32_t* c = cK[kb & 3];
            #pragma unroll
            for (int ni = 0; ni < 8; ni++) {
                bf[ni][0] = *(const uint32_t*)(bb + rBbase + ni * 1024 + c[0]);
                bf[ni][1] = *(const uint32_t*)(bb + rBbase + ni * 1024 + c[1]);
            }
        };
        auto mmab = [&](const uint32_t af[2][4], const uint32_t bf[8][2]) {
            #pragma unroll
            for (int mi = 0; mi < 2; mi++)
                #pragma unroll
                for (int ni = 0; ni < 8; ni++)
                    mma_f16(acc[mi][ni], af[mi], bf[ni][0], bf[ni][1]);
        };

        int ss = 0, ph = 0;
        const char* astg = smem + SM2_A;
        const char* bstg = smem + SM2_B;

        MBAR_WAIT(base + SM_FULL, 0u);
        ldB(Bf[0], bstg, 0);
        ldA(Af[0], astg, 0);

        for (int i = 0; i < S2ITERS; i++) {
            #pragma unroll
            for (int kb = 0; kb < 8; kb++) {
                if (kb < 7) {
                    const int nb = (kb + 1) & 1;
                    ldB(Bf[nb], bstg, kb + 1);
                    ldA(Af[nb], astg, kb + 1);
                    mmab(Af[kb & 1], Bf[kb & 1]);
                } else {
                    mmab(Af[1], Bf[1]);
                    if (lane == 0) MBAR_ARRIVE(base + SM_DONE + ss * 8);
                    int ssn = ss + 1, phn = ph;
                    if (ssn == S2STAGES) { ssn = 0; phn ^= 1; }
                    if (i < S2ITERS - 1) {
                        MBAR_WAIT(base + SM_FULL + ssn * 8, (uint32_t)phn);
                        astg = smem + SM2_A + ssn * A2_SS_BYTES;
                        bstg = smem + SM2_B + ssn * B2_SS_BYTES;
                        ldB(Bf[0], bstg, 0);
                        ldA(Af[0], astg, 0);
                    }
                    ss = ssn; ph = phn;
                }
            }
        }

        #pragma unroll
        for (int ni = 0; ni < 8; ni++) {
            const int c0 = wn * 64 + ni * 8 + tg * 2;
            const float bb0 = __ldg(&bias[c0]);
            const float bb1 = __ldg(&bias[c0 + 1]);
            #pragma unroll
            for (int mi = 0; mi < 2; mi++) {
                const int r0 = m0 + wm * 32 + mi * 16 + g;
                float2 v0, v1;
                v0.x = fmaxf(acc[mi][ni][0] + bb0, 0.0f);
                v0.y = fmaxf(acc[mi][ni][1] + bb1, 0.0f);
                v1.x = fmaxf(acc[mi][ni][2] + bb0, 0.0f);
                v1.y = fmaxf(acc[mi][ni][3] + bb1, 0.0f);
                *reinterpret_cast<float2*>(out + (size_t)r0 * HDIM + c0) = v0;
                *reinterpret_cast<float2*>(out + (size_t)(r0 + 8) * HDIM + c0) = v1;
            }
        }
    }
}

// ===================== small GEMM: outT[n][node] = sum_f in[node][f] * w[f][n] (fp16 out) =====================
__global__ void __launch_bounds__(256)
gcn_in_gemm(const float* __restrict__ in, const float* __restrict__ w, __half* __restrict__ outT) {
    extern __shared__ float sm[];
    float* ws = sm;
    float* xs = sm + HDIM * HDIM;
    const int tid = threadIdx.x;
    const int n0 = blockIdx.x * 128;

    for (int i = tid; i < (HDIM * HDIM) / 4; i += 256)
        reinterpret_cast<float4*>(ws)[i] = reinterpret_cast<const float4*>(w)[i];
    {
        const int col = tid & 127;
        const int r0  = tid >> 7;
        for (int r = r0; r < 128; r += 2)
            xs[r * XS_PAD + col] = in[(size_t)(n0 + r) * HDIM + col];
    }
    __syncthreads();

    const int cg   = tid >> 5;
    const int lane = tid & 31;

    float acc[4][16];
    #pragma unroll
    for (int k = 0; k < 4; k++)
        #pragma unroll
        for (int j = 0; j < 16; j++) acc[k][j] = 0.0f;

    #pragma unroll 4
    for (int f = 0; f < HDIM; f++) {
        float a[4];
        #pragma unroll
        for (int k = 0; k < 4; k++)
            a[k] = xs[(lane + 32 * k) * XS_PAD + f];
        const float4* wr = reinterpret_cast<const float4*>(ws + f * HDIM + cg * 16);
        float4 w0 = wr[0], w1 = wr[1], w2 = wr[2], w3 = wr[3];
        #pragma unroll
        for (int k = 0; k < 4; k++) {
            acc[k][0]  += a[k] * w0.x;  acc[k][1]  += a[k] * w0.y;
            acc[k][2]  += a[k] * w0.z;  acc[k][3]  += a[k] * w0.w;
            acc[k][4]  += a[k] * w1.x;  acc[k][5]  += a[k] * w1.y;
            acc[k][6]  += a[k] * w1.z;  acc[k][7]  += a[k] * w1.w;
            acc[k][8]  += a[k] * w2.x;  acc[k][9]  += a[k] * w2.y;
            acc[k][10] += a[k] * w2.z;  acc[k][11] += a[k] * w2.w;
            acc[k][12] += a[k] * w3.x;  acc[k][13] += a[k] * w3.y;
            acc[k][14] += a[k] * w3.z;  acc[k][15] += a[k] * w3.w;
        }
    }
    #pragma unroll
    for (int j = 0; j < 16; j++) {
        const int col = cg * 16 + j;
        #pragma unroll
        for (int k = 0; k < 4; k++)
            outT[(size_t)col * NNODES + n0 + lane + 32 * k] = __float2half_rn(acc[k][j]);
    }
}

// ===================== head =====================
__global__ void __launch_bounds__(256)
gcn_head(const float* __restrict__ h, const float* __restrict__ w3,
         const float* __restrict__ b3, float* __restrict__ out) {
    const int i = blockIdx.x * 256 + threadIdx.x;
    if (i >= NNODES) return;
    float s0 = __ldg(&b3[0]), s1 = __ldg(&b3[1]);
    const float4* hv = reinterpret_cast<const float4*>(h + (size_t)i * HDIM);
    #pragma unroll
    for (int q = 0; q < 32; q++) {
        float4 v = __ldg(&hv[q]);
        const int n = q * 4;
        s0 += v.x * __ldg(&w3[(n + 0) * 2 + 0]); s1 += v.x * __ldg(&w3[(n + 0) * 2 + 1]);
        s0 += v.y * __ldg(&w3[(n + 1) * 2 + 0]); s1 += v.y * __ldg(&w3[(n + 1) * 2 + 1]);
        s0 += v.z * __ldg(&w3[(n + 2) * 2 + 0]); s1 += v.z * __ldg(&w3[(n + 2) * 2 + 1]);
        s0 += v.w * __ldg(&w3[(n + 3) * 2 + 0]); s1 += v.w * __ldg(&w3[(n + 3) * 2 + 1]);
    }
    out[i * 2 + 0] = s0;
    out[i * 2 + 1] = s1;
}

// ===================== host =====================
typedef CUresult (*PFN_encodeTiled)(CUtensorMap*, CUtensorMapDataType, cuuint32_t, void*,
                                    const cuuint64_t*, const cuuint64_t*, const cuuint32_t*,
                                    const cuuint32_t*, CUtensorMapInterleave, CUtensorMapSwizzle,
                                    CUtensorMapL2promotion, CUtensorMapFloatOOBfill);

extern "C" void kernel_launch(void* const* d_in, const int* in_sizes, int n_in,
                              void* d_out, int out_size) {
    const float* x   = (const float*)d_in[0];
    const float* adj = (const float*)d_in[1];
    const float* w1  = (const float*)d_in[2];
    const float* b1  = (const float*)d_in[3];
    const float* w2  = (const float*)d_in[4];
    const float* b2  = (const float*)d_in[5];
    const float* w3  = (const float*)d_in[6];
    const float* b3  = (const float*)d_in[7];
    float* out = (float*)d_out;

    void *bufA16 = nullptr, *bufB = nullptr, *bufH = nullptr;
    cudaGetSymbolAddress(&bufA16, g_bufA16);
    cudaGetSymbolAddress(&bufB, g_bufB);
    cudaGetSymbolAddress(&bufH, g_bufH);

    void* fn = nullptr;
    cudaDriverEntryPointQueryResult qres;
    cudaGetDriverEntryPointByVersion("cuTensorMapEncodeTiled", &fn, 12000,
                                     cudaEnableDefault, &qres);
    PFN_encodeTiled encode = (PFN_encodeTiled)fn;

    CUtensorMap tmA{}, tmB{}, tmA16{};
    {
        cuuint64_t dims[2]   = {NNODES, NNODES};
        cuuint64_t stride[1] = {NNODES * sizeof(float)};
        cuuint32_t box[2]    = {32, TILE_M};
        cuuint32_t es[2]     = {1, 1};
        encode(&tmA, CU_TENSOR_MAP_DATA_TYPE_FLOAT32, 2, (void*)adj, dims, stride, box, es,
               CU_TENSOR_MAP_INTERLEAVE_NONE, CU_TENSOR_MAP_SWIZZLE_128B,
               CU_TENSOR_MAP_L2_PROMOTION_L2_128B, CU_TENSOR_MAP_FLOAT_OOB_FILL_NONE);
    }
    {
        cuuint64_t dims[2]   = {NNODES, HDIM};
        cuuint64_t stride[1] = {NNODES * sizeof(__half)};
        cuuint32_t box[2]    = {64, TILE_N};
        cuuint32_t es[2]     = {1, 1};
        encode(&tmB, CU_TENSOR_MAP_DATA_TYPE_FLOAT16, 2, bufB, dims, stride, box, es,
               CU_TENSOR_MAP_INTERLEAVE_NONE, CU_TENSOR_MAP_SWIZZLE_128B,
               CU_TENSOR_MAP_L2_PROMOTION_L2_128B, CU_TENSOR_MAP_FLOAT_OOB_FILL_NONE);
    }
    {
        cuuint64_t dims[2]   = {NNODES, NNODES};
        cuuint64_t stride[1] = {NNODES * sizeof(__half)};
        cuuint32_t box[2]    = {64, TILE_M};
        cuuint32_t es[2]     = {1, 1};
        encode(&tmA16, CU_TENSOR_MAP_DATA_TYPE_FLOAT16, 2, bufA16, dims, stride, box, es,
               CU_TENSOR_MAP_INTERLEAVE_NONE, CU_TENSOR_MAP_SWIZZLE_128B,
               CU_TENSOR_MAP_L2_PROMOTION_L2_128B, CU_TENSOR_MAP_FLOAT_OOB_FILL_NONE);
    }

    cudaFuncSetAttribute(gcn_big_gemm1, cudaFuncAttributeMaxDynamicSharedMemorySize, SMEM_TOTAL);
    cudaFuncSetAttribute(gcn_big_gemm2, cudaFuncAttributeMaxDynamicSharedMemorySize, SMEM2_TOTAL);
    cudaFuncSetAttribute(gcn_in_gemm, cudaFuncAttributeMaxDynamicSharedMemorySize, IN_SMEM);

    // 1) t1^T (fp16)
    gcn_in_gemm<<<NNODES / 128, 256, IN_SMEM>>>(x, w1, (__half*)bufB);
    // 2) h1 = relu(adj @ t1 + b1)  + fused smem->fp16 adjacency writeback
    gcn_big_gemm1<<<NNODES / TILE_M, BIG1_THREADS, SMEM_TOTAL>>>(
        tmA, tmB, b1, (float*)bufH, (__half*)bufA16);
    // 3) t2^T (fp16)
    gcn_in_gemm<<<NNODES / 128, 256, IN_SMEM>>>((const float*)bufH, w2, (__half*)bufB);
    // 4) h2 = relu(adj16 @ t2 + b2)  (all-fp16 operands)
    gcn_big_gemm2<<<NNODES / TILE_M, BIG2_THREADS, SMEM2_TOTAL>>>(
        tmA16, tmB, b2, (float*)bufH);
    // 5) out = h2 @ w3 + b3
    gcn_head<<<NNODES / 256, 256>>>((const float*)bufH, w3, b3, out);
}

// round 12
// speedup vs baseline: 3.3701x; 1.3764x over previous
#include <cuda_runtime.h>
#include <cuda.h>
#include <cuda_fp16.h>
#include <cstdint>

// ===================== constants =====================
#define NNODES   16384
#define HDIM     128
#define TILE_M   128
#define TILE_N   128
#define KSUPER   64             // K elems per super-stage (2 fp32 A boxes + 1 fp16 B box)
#define SSTAGES  4
#define SITERS   (NNODES / KSUPER)   // 256

#define A_SS_BYTES (TILE_M * KSUPER * 4)   // 32768 (fp32)
#define B_SS_BYTES (TILE_N * KSUPER * 2)   // 16384 (fp16)
#define SS_TX      (A_SS_BYTES + B_SS_BYTES)  // 49152

// smem layout (dynamic)
#define SM_FULL    0      // SSTAGES mbarriers (8B each)
#define SM_DONE    64     // SSTAGES mbarriers
#define SM_A       1024
#define SM_B       (SM_A + SSTAGES * A_SS_BYTES)     // 132096
#define SMEM_TOTAL (SM_B + SSTAGES * B_SS_BYTES)     // 197632

#define BIG_THREADS 288   // warps 0-7 compute (4x2 grid of 32x64 tiles), warp 8 TMA

// in_gemm smem: w tile 128x128 + x tile 128x129 (pad -> conflict-free)
#define XS_PAD  129
#define IN_SMEM ((HDIM * HDIM + HDIM * XS_PAD) * 4)   // 131584

// scratch (allocation-free rule: __device__ globals)
__device__ __align__(1024) __half g_bufB[128UL * 16384];  // t1^T / t2^T  [H][N] fp16
__device__ __align__(1024) float  g_bufH[16384UL * 128];  // h1 / h2      [N][H]

// ===================== PTX helpers =====================
__device__ __forceinline__ uint32_t smem_u32(const void* p) {
    uint32_t a;
    asm("{ .reg .u64 t; cvta.to.shared.u64 t, %1; cvt.u32.u64 %0, t; }" : "=r"(a) : "l"(p));
    return a;
}

#define MBAR_INIT(addr, cnt) \
    asm volatile("mbarrier.init.shared.b64 [%0], %1;" :: "r"(addr), "r"(cnt) : "memory")
#define MBAR_EXPECT_TX(addr, bytes) \
    asm volatile("mbarrier.arrive.expect_tx.shared.b64 _, [%0], %1;" :: "r"(addr), "r"(bytes) : "memory")
#define MBAR_ARRIVE(addr) \
    asm volatile("mbarrier.arrive.shared.b64 _, [%0];" :: "r"(addr) : "memory")

#define MBAR_WAIT(addr, parity) do {                                            \
    uint32_t _m = (addr), _p = (parity), _d;                                    \
    asm volatile("{\n\t.reg .pred p;\n\t"                                       \
        "mbarrier.try_wait.parity.acquire.cta.shared::cta.b64 p, [%1], %2;\n\t" \
        "selp.b32 %0, 1, 0, p;\n\t}" : "=r"(_d) : "r"(_m), "r"(_p) : "memory"); \
    if (!_d) {                                                                  \
        asm volatile("{\n\t.reg .pred P1;\n\t"                                  \
        "WL%=:\n\t"                                                             \
        "mbarrier.try_wait.parity.acquire.cta.shared::cta.b64 P1, [%0], %1, 0x989680;\n\t" \
        "@P1 bra.uni WD%=;\n\t"                                                 \
        "bra.uni WL%=;\n\t"                                                     \
        "WD%=:\n\t}" :: "r"(_m), "r"(_p) : "memory");                           \
    } } while (0)

__device__ __forceinline__ void tma_2d(uint32_t smem_dst, const CUtensorMap* map,
                                       int32_t cx, int32_t cy, uint32_t mbar) {
    asm volatile(
        "cp.async.bulk.tensor.2d.shared::cta.global.tile.mbarrier::complete_tx::bytes "
        "[%0], [%1, {%2, %3}], [%4];"
        :: "r"(smem_dst), "l"(map), "r"(cx), "r"(cy), "r"(mbar) : "memory");
}

// pack two fp32 -> f16x2 {lo=a, hi=b}
__device__ __forceinline__ uint32_t pack_f16x2(float a, float b) {
    uint32_t r;
    asm("cvt.rn.f16x2.f32 %0, %1, %2;" : "=r"(r) : "f"(b), "f"(a));
    return r;
}

__device__ __forceinline__ void mma_f16(float* c, const uint32_t* a, uint32_t b0, uint32_t b1) {
    asm volatile("mma.sync.aligned.m16n8k16.row.col.f32.f16.f16.f32 "
        "{%0,%1,%2,%3}, {%4,%5,%6,%7}, {%8,%9}, {%0,%1,%2,%3};"
        : "+f"(c[0]), "+f"(c[1]), "+f"(c[2]), "+f"(c[3])
        : "r"(a[0]), "r"(a[1]), "r"(a[2]), "r"(a[3]), "r"(b0), "r"(b1));
}

// ===================== big GEMM =====================
// out[m][n] = relu(bias[n] + sum_k A[m][k]*Bt[n][k])
// 8 compute warps, 4x2 grid of 32x64 warp tiles, warp 8 TMA.
// fp16 m16n8k16; A fp32 in smem (raw LDS.64 + pair-pack cvt), B fp16 in smem.
// Lookahead-2 register pipeline with MMA-first issue order: the FULL(next)
// wait + next-stage block-0/1 loads hide under blocks 2/3's MMA drain.

__global__ void __launch_bounds__(BIG_THREADS, 1)
gcn_big_gemm(const __grid_constant__ CUtensorMap tmA,
             const __grid_constant__ CUtensorMap tmB,
             const float* __restrict__ bias,
             float* __restrict__ out) {
    extern __shared__ __align__(1024) char smem[];
    const uint32_t base = smem_u32(smem);
    const int tid  = threadIdx.x;
    const int wid  = tid >> 5;
    const int lane = tid & 31;
    const int m0   = blockIdx.x * TILE_M;

    if (tid == 0) {
        for (int s = 0; s < SSTAGES; s++) {
            MBAR_INIT(base + SM_FULL + s * 8, 1);
            MBAR_INIT(base + SM_DONE + s * 8, 8);
        }
    }
    __syncthreads();

    if (wid == 8) {
        // -------- TMA producer --------
        if (lane == 0) {
            const CUtensorMap* pA = &tmA;
            const CUtensorMap* pB = &tmB;
            int ss = 0, ph = 1;
            for (int i = 0; i < SITERS; i++) {
                MBAR_WAIT(base + SM_DONE + ss * 8, (uint32_t)ph);
                uint32_t full = base + SM_FULL + ss * 8;
                MBAR_EXPECT_TX(full, SS_TX);
                uint32_t aslot = base + SM_A + ss * A_SS_BYTES;
                uint32_t bslot = base + SM_B + ss * B_SS_BYTES;
                int k0 = i * KSUPER;
                tma_2d(aslot,         pA, k0,      m0, full);
                tma_2d(aslot + 16384, pA, k0 + 32, m0, full);
                tma_2d(bslot,         pB, k0,      0,  full);
                if (++ss == SSTAGES) { ss = 0; ph ^= 1; }
            }
        }
    } else {
        // -------- compute warps --------
        const int g  = lane >> 2;     // 0..7
        const int tg = lane & 3;      // 0..3
        const int wm = wid >> 1;      // 0..3  (m: 32-row band)
        const int wn = wid & 1;       // 0..1  (n: 64-col band)
        const uint32_t xorv = (uint32_t)g << 4;

        const uint32_t rAbase = (uint32_t)(wm * 32 + g) * 128;  // + mi*2048 (+1024 for row+8)
        const uint32_t rBbase = (uint32_t)(wn * 64 + g) * 128;  // + ni*1024

        // A cols per k16-half sel (kb&1), two k8 sub-halves
        uint32_t cA[2][2];
        #pragma unroll
        for (int s = 0; s < 2; s++) {
            cA[s][0] = ((uint32_t)(s * 64 + 8 * tg)) ^ xorv;        // k = 2tg..
            cA[s][1] = ((uint32_t)(s * 64 + 8 * tg + 32)) ^ xorv;   // k+8
        }
        // B cols per k16 block kb (0..3)
        uint32_t cB[4][2];
        #pragma unroll
        for (int kb = 0; kb < 4; kb++) {
            cB[kb][0] = ((uint32_t)(32 * kb + 4 * tg)) ^ xorv;
            cB[kb][1] = ((uint32_t)(32 * kb + 16 + 4 * tg)) ^ xorv;
        }

        float acc[2][8][4];
        #pragma unroll
        for (int mi = 0; mi < 2; mi++)
            #pragma unroll
            for (int ni = 0; ni < 8; ni++)
                #pragma unroll
                for (int q = 0; q < 4; q++) acc[mi][ni][q] = 0.0f;

        uint32_t Af[2][2][4];   // [buf][mi][reg]
        uint32_t Bf[2][8][2];   // [buf][ni][reg]

        // fragment loaders (kb = k16 block 0..3)
        auto ldA = [&](uint32_t af[2][4], const char* astg, int kb) {
            const char* ab = astg + ((kb >> 1) << 14);
            const uint32_t* c = cA[kb & 1];
            #pragma unroll
            for (int mi = 0; mi < 2; mi++) {
                const char* r0 = ab + rAbase + mi * 2048;
                uint2 lo0 = *(const uint2*)(r0 + c[0]);
                uint2 lo1 = *(const uint2*)(r0 + 1024 + c[0]);
                uint2 hi0 = *(const uint2*)(r0 + c[1]);
                uint2 hi1 = *(const uint2*)(r0 + 1024 + c[1]);
                af[mi][0] = pack_f16x2(__uint_as_float(lo0.x), __uint_as_float(lo0.y));
                af[mi][1] = pack_f16x2(__uint_as_float(lo1.x), __uint_as_float(lo1.y));
                af[mi][2] = pack_f16x2(__uint_as_float(hi0.x), __uint_as_float(hi0.y));
                af[mi][3] = pack_f16x2(__uint_as_float(hi1.x), __uint_as_float(hi1.y));
            }
        };
        auto ldB = [&](uint32_t bf[8][2], const char* bstg, int kb) {
            #pragma unroll
            for (int ni = 0; ni < 8; ni++) {
                bf[ni][0] = *(const uint32_t*)(bstg + rBbase + ni * 1024 + cB[kb][0]);
                bf[ni][1] = *(const uint32_t*)(bstg + rBbase + ni * 1024 + cB[kb][1]);
            }
        };
        auto mmab = [&](const uint32_t af[2][4], const uint32_t bf[8][2]) {
            #pragma unroll
            for (int mi = 0; mi < 2; mi++)
                #pragma unroll
                for (int ni = 0; ni < 8; ni++)
                    mma_f16(acc[mi][ni], af[mi], bf[ni][0], bf[ni][1]);
        };

        int ss = 0, ph = 0;
        const char* astg = smem + SM_A;
        const char* bstg = smem + SM_B;

        // prologue: blocks 0 and 1 of stage 0
        MBAR_WAIT(base + SM_FULL, 0u);
        ldB(Bf[0], bstg, 0);
        ldA(Af[0], astg, 0);
        ldB(Bf[1], bstg, 1);
        ldA(Af[1], astg, 1);

        for (int i = 0; i < SITERS; i++) {
            // kb0: mma first, then load kb2 (WAR on buf0 is scoreboard-safe)
            mmab(Af[0], Bf[0]);
            ldB(Bf[0], bstg, 2);
            ldA(Af[0], astg, 2);
            // kb1: mma, then load kb3
            mmab(Af[1], Bf[1]);
            ldB(Bf[1], bstg, 3);
            ldA(Af[1], astg, 3);
            // kb2: mma, then wait next stage + load its block 0
            mmab(Af[0], Bf[0]);
            int ssn = ss + 1, phn = ph;
            if (ssn == SSTAGES) { ssn = 0; phn ^= 1; }
            const char* nastg = smem + SM_A + ssn * A_SS_BYTES;
            const char* nbstg = smem + SM_B + ssn * B_SS_BYTES;
            if (i < SITERS - 1) {
                MBAR_WAIT(base + SM_FULL + ssn * 8, (uint32_t)phn);
                ldB(Bf[0], nbstg, 0);
                ldA(Af[0], nastg, 0);
            }
            // kb3: mma (operand scoreboard proves stage-ss LDS all done), arrive,
            // then load next stage block 1
            mmab(Af[1], Bf[1]);
            if (lane == 0) MBAR_ARRIVE(base + SM_DONE + ss * 8);
            if (i < SITERS - 1) {
                ldB(Bf[1], nbstg, 1);
                ldA(Af[1], nastg, 1);
            }
            astg = nastg; bstg = nbstg; ss = ssn; ph = phn;
        }

        // -------- epilogue: bias + relu, write fp32 --------
        #pragma unroll
        for (int ni = 0; ni < 8; ni++) {
            const int c0 = wn * 64 + ni * 8 + tg * 2;
            const float bb0 = __ldg(&bias[c0]);
            const float bb1 = __ldg(&bias[c0 + 1]);
            #pragma unroll
            for (int mi = 0; mi < 2; mi++) {
                const int r0 = m0 + wm * 32 + mi * 16 + g;
                float2 v0, v1;
                v0.x = fmaxf(acc[mi][ni][0] + bb0, 0.0f);
                v0.y = fmaxf(acc[mi][ni][1] + bb1, 0.0f);
                v1.x = fmaxf(acc[mi][ni][2] + bb0, 0.0f);
                v1.y = fmaxf(acc[mi][ni][3] + bb1, 0.0f);
                *reinterpret_cast<float2*>(out + (size_t)r0 * HDIM + c0) = v0;
                *reinterpret_cast<float2*>(out + (size_t)(r0 + 8) * HDIM + c0) = v1;
            }
        }
    }
}

// ===================== small GEMM: outT[n][node] = sum_f in[node][f] * w[f][n] =====================
// Output stored as fp16 (RN) = pre-rounded B operand for the big GEMM.
__global__ void __launch_bounds__(256)
gcn_in_gemm(const float* __restrict__ in, const float* __restrict__ w, __half* __restrict__ outT) {
    extern __shared__ float sm[];
    float* ws = sm;                       // [128][128]
    float* xs = sm + HDIM * HDIM;         // [128][129] padded
    const int tid = threadIdx.x;
    const int n0 = blockIdx.x * 128;

    for (int i = tid; i < (HDIM * HDIM) / 4; i += 256)
        reinterpret_cast<float4*>(ws)[i] = reinterpret_cast<const float4*>(w)[i];
    {
        const int col = tid & 127;
        const int r0  = tid >> 7;
        for (int r = r0; r < 128; r += 2)
            xs[r * XS_PAD + col] = in[(size_t)(n0 + r) * HDIM + col];
    }
    __syncthreads();

    const int cg   = tid >> 5;
    const int lane = tid & 31;

    float acc[4][16];
    #pragma unroll
    for (int k = 0; k < 4; k++)
        #pragma unroll
        for (int j = 0; j < 16; j++) acc[k][j] = 0.0f;

    #pragma unroll 4
    for (int f = 0; f < HDIM; f++) {
        float a[4];
        #pragma unroll
        for (int k = 0; k < 4; k++)
            a[k] = xs[(lane + 32 * k) * XS_PAD + f];
        const float4* wr = reinterpret_cast<const float4*>(ws + f * HDIM + cg * 16);
        float4 w0 = wr[0], w1 = wr[1], w2 = wr[2], w3 = wr[3];
        #pragma unroll
        for (int k = 0; k < 4; k++) {
            acc[k][0]  += a[k] * w0.x;  acc[k][1]  += a[k] * w0.y;
            acc[k][2]  += a[k] * w0.z;  acc[k][3]  += a[k] * w0.w;
            acc[k][4]  += a[k] * w1.x;  acc[k][5]  += a[k] * w1.y;
            acc[k][6]  += a[k] * w1.z;  acc[k][7]  += a[k] * w1.w;
            acc[k][8]  += a[k] * w2.x;  acc[k][9]  += a[k] * w2.y;
            acc[k][10] += a[k] * w2.z;  acc[k][11] += a[k] * w2.w;
            acc[k][12] += a[k] * w3.x;  acc[k][13] += a[k] * w3.y;
            acc[k][14] += a[k] * w3.z;  acc[k][15] += a[k] * w3.w;
        }
    }
    #pragma unroll
    for (int j = 0; j < 16; j++) {
        const int col = cg * 16 + j;
        #pragma unroll
        for (int k = 0; k < 4; k++)
            outT[(size_t)col * NNODES + n0 + lane + 32 * k] = __float2half_rn(acc[k][j]);
    }
}

// ===================== head: out[i][c] = b3[c] + sum_n h[i][n] * w3[n][c] =====================
__global__ void __launch_bounds__(256)
gcn_head(const float* __restrict__ h, const float* __restrict__ w3,
         const float* __restrict__ b3, float* __restrict__ out) {
    const int i = blockIdx.x * 256 + threadIdx.x;
    if (i >= NNODES) return;
    float s0 = __ldg(&b3[0]), s1 = __ldg(&b3[1]);
    const float4* hv = reinterpret_cast<const float4*>(h + (size_t)i * HDIM);
    #pragma unroll
    for (int q = 0; q < 32; q++) {
        float4 v = __ldg(&hv[q]);
        const int n = q * 4;
        s0 += v.x * __ldg(&w3[(n + 0) * 2 + 0]); s1 += v.x * __ldg(&w3[(n + 0) * 2 + 1]);
        s0 += v.y * __ldg(&w3[(n + 1) * 2 + 0]); s1 += v.y * __ldg(&w3[(n + 1) * 2 + 1]);
        s0 += v.z * __ldg(&w3[(n + 2) * 2 + 0]); s1 += v.z * __ldg(&w3[(n + 2) * 2 + 1]);
        s0 += v.w * __ldg(&w3[(n + 3) * 2 + 0]); s1 += v.w * __ldg(&w3[(n + 3) * 2 + 1]);
    }
    out[i * 2 + 0] = s0;
    out[i * 2 + 1] = s1;
}

// ===================== host =====================
typedef CUresult (*PFN_encodeTiled)(CUtensorMap*, CUtensorMapDataType, cuuint32_t, void*,
                                    const cuuint64_t*, const cuuint64_t*, const cuuint32_t*,
                                    const cuuint32_t*, CUtensorMapInterleave, CUtensorMapSwizzle,
                                    CUtensorMapL2promotion, CUtensorMapFloatOOBfill);

extern "C" void kernel_launch(void* const* d_in, const int* in_sizes, int n_in,
                              void* d_out, int out_size) {
    const float* x   = (const float*)d_in[0];
    const float* adj = (const float*)d_in[1];
    const float* w1  = (const float*)d_in[2];
    const float* b1  = (const float*)d_in[3];
    const float* w2  = (const float*)d_in[4];
    const float* b2  = (const float*)d_in[5];
    const float* w3  = (const float*)d_in[6];
    const float* b3  = (const float*)d_in[7];
    float* out = (float*)d_out;

    void* bufB = nullptr;
    void* bufH = nullptr;
    cudaGetSymbolAddress(&bufB, g_bufB);
    cudaGetSymbolAddress(&bufH, g_bufH);

    void* fn = nullptr;
    cudaDriverEntryPointQueryResult qres;
    cudaGetDriverEntryPointByVersion("cuTensorMapEncodeTiled", &fn, 12000,
                                     cudaEnableDefault, &qres);
    PFN_encodeTiled encode = (PFN_encodeTiled)fn;

    CUtensorMap tmA{}, tmB{};
    {
        cuuint64_t dims[2]   = {NNODES, NNODES};
        cuuint64_t stride[1] = {NNODES * sizeof(float)};
        cuuint32_t box[2]    = {32, TILE_M};
        cuuint32_t es[2]     = {1, 1};
        encode(&tmA, CU_TENSOR_MAP_DATA_TYPE_FLOAT32, 2, (void*)adj, dims, stride, box, es,
               CU_TENSOR_MAP_INTERLEAVE_NONE, CU_TENSOR_MAP_SWIZZLE_128B,
               CU_TENSOR_MAP_L2_PROMOTION_L2_128B, CU_TENSOR_MAP_FLOAT_OOB_FILL_NONE);
    }
    {
        cuuint64_t dims[2]   = {NNODES, HDIM};
        cuuint64_t stride[1] = {NNODES * sizeof(__half)};
        cuuint32_t box[2]    = {64, TILE_N};   // 64 f16 = 128B rows (SW128)
        cuuint32_t es[2]     = {1, 1};
        encode(&tmB, CU_TENSOR_MAP_DATA_TYPE_FLOAT16, 2, bufB, dims, stride, box, es,
               CU_TENSOR_MAP_INTERLEAVE_NONE, CU_TENSOR_MAP_SWIZZLE_128B,
               CU_TENSOR_MAP_L2_PROMOTION_L2_128B, CU_TENSOR_MAP_FLOAT_OOB_FILL_NONE);
    }

    cudaFuncSetAttribute(gcn_big_gemm, cudaFuncAttributeMaxDynamicSharedMemorySize, SMEM_TOTAL);
    cudaFuncSetAttribute(gcn_in_gemm, cudaFuncAttributeMaxDynamicSharedMemorySize, IN_SMEM);

    // 1) t1^T (fp16)
    gcn_in_gemm<<<NNODES / 128, 256, IN_SMEM>>>(x, w1, (__half*)bufB);
    // 2) h1 = relu(adj @ t1 + b1)
    gcn_big_gemm<<<NNODES / TILE_M, BIG_THREADS, SMEM_TOTAL>>>(tmA, tmB, b1, (float*)bufH);
    // 3) t2^T (fp16)
    gcn_in_gemm<<<NNODES / 128, 256, IN_SMEM>>>((const float*)bufH, w2, (__half*)bufB);
    // 4) h2 = relu(adj @ t2 + b2)
    gcn_big_gemm<<<NNODES / TILE_M, BIG_THREADS, SMEM_TOTAL>>>(tmA, tmB, b2, (float*)bufH);
    // 5) out = h2 @ w3 + b3
    gcn_head<<<NNODES / 256, 256>>>((const float*)bufH, w3, b3, out);
}